// round 16
// baseline (speedup 1.0000x reference)
#include <cuda_runtime.h>
#include <cuda_bf16.h>

// LineRaster2d: canvas[x][y] = LINE_WIDTH - dist if dist(point,segment) < LINE_WIDTH else 0
// H = W = 6144, LINE_WIDTH = 1.0
//
// FINAL (frozen best): one block per row (grid=6144, TPB=384, 4 float4/thread).
// Spans outside the row's conservative non-zero band (>99.9% of the canvas)
// are pure coalesced STG.128 zero stores; spans inside evaluate the exact
// reference formula. Empty band is encoded as the sentinel interval [0,-1].
//
// Convergence evidence: each replay dirties the full 151 MB canvas, which
// must drain to DRAM once per replay period -> 151 MB / 25.3us = ~5.97 TB/s
// sustained DRAM write. Eight kernel variants (TPB 256/384/512, persistent
// grid, int-span test, .cs stores, uniform fast-path, two-kernel split,
// sentinel encoding) all measured within the 25.06-25.73us run-noise band
// with an invariant ncu signature (DRAM ~51%, L2 ~56%, issue ~40%, no pipe
// saturated). The output byte count is fixed by the problem, so the replay
// period is pinned by write-drain bandwidth and this kernel is final.

#define H 6144
#define W 6144
#define ROW_F4 (W / 4)          // 1536 float4 per row
#define TPB    384              // 4 float4 per thread

__global__ void __launch_bounds__(TPB) raster_fused_kernel(
    const float* __restrict__ p0_in,
    const float* __restrict__ p1_in,
    float4* __restrict__ out)
{
    const int x = blockIdx.x;           // row
    const int t = threadIdx.x;

    // Segment constants (broadcast loads)
    float p0x = p0_in[0] * (float)H;
    float p0y = p0_in[1] * (float)W;
    float p1x = p1_in[0] * (float)H;
    float p1y = p1_in[1] * (float)W;

    float dx = p1x - p0x;
    float dy = p1y - p0y;
    float len_sq  = dx * dx + dy * dy;
    float inv_len = 1.0f / len_sq;

    float X = (float)x;

    // Conservative band for this row: any pixel (X,y) with dist<1 has its
    // nearest segment point s with |X-sx|<1 and |y-sy|<1. Restrict the segment
    // to sx in (X-1, X+1) -> t-range [tlo,thi]; nonzero y lies within 1 of
    // that sub-segment's y-extent. Empty band -> sentinel [0, -1].
    float ylo = 0.0f, yhi = -1.0f;
    {
        bool has_band;
        float tlo, thi;
        if (fabsf(dx) > 1e-12f) {
            float ta = (X - 1.0f - p0x) / dx;
            float tb = (X + 1.0f - p0x) / dx;
            tlo = fmaxf(fminf(ta, tb), 0.0f);
            thi = fminf(fmaxf(ta, tb), 1.0f);
            has_band = (tlo <= thi);
        } else {
            has_band = (fabsf(X - p0x) < 1.0f);
            tlo = 0.0f; thi = 1.0f;
        }
        if (has_band) {
            float ya = fmaf(tlo, dy, p0y);
            float yb = fmaf(thi, dy, p0y);
            ylo = fminf(ya, yb) - 1.0f;
            yhi = fmaxf(ya, yb) + 1.0f;
        }
    }

    float px  = X - p0x;
    float pxd = px * dx;                      // constant part of dot product

    float4* __restrict__ row = out + (size_t)x * ROW_F4;

    #pragma unroll
    for (int s = 0; s < 4; s++) {             // 4 * 384 = 1536 = ROW_F4
        int   f4 = t + s * TPB;               // float4 index within row
        float a  = (float)(f4 << 2);          // first y of this 4-pixel span

        float4 v = make_float4(0.f, 0.f, 0.f, 0.f);

        // Span [a, a+3] can only hold non-zeros if it meets [ylo, yhi]
        // (unsatisfiable for the sentinel interval).
        if ((yhi >= a) && (ylo <= a + 3.0f)) {
            float* vp = &v.x;
            #pragma unroll
            for (int j = 0; j < 4; j++) {
                float Y  = a + (float)j;
                float py = Y - p0y;
                float tt = (pxd + py * dy) * inv_len;
                tt = fminf(fmaxf(tt, 0.0f), 1.0f);
                float projx = fmaf(tt, dx, p0x);
                float projy = fmaf(tt, dy, p0y);
                float ex = X - projx;
                float ey = Y - projy;
                float dist_sq = ex * ex + ey * ey;
                if (dist_sq < 1.0f) {
                    vp[j] = 1.0f - sqrtf(dist_sq);
                }
            }
        }

        row[f4] = v;                          // coalesced STG.128
    }
}

extern "C" void kernel_launch(void* const* d_in, const int* in_sizes, int n_in,
                              void* d_out, int out_size) {
    (void)in_sizes; (void)n_in; (void)out_size;
    const float* p0 = (const float*)d_in[0];
    const float* p1 = (const float*)d_in[1];
    float4* out = (float4*)d_out;

    raster_fused_kernel<<<H, TPB>>>(p0, p1, out);
}

// round 17
// speedup vs baseline: 1.0498x; 1.0498x over previous
#include <cuda_runtime.h>
#include <cuda_bf16.h>

// LineRaster2d: canvas[x][y] = LINE_WIDTH - dist if dist(point,segment) < LINE_WIDTH else 0
// H = W = 6144, LINE_WIDTH = 1.0
//
// FINAL (frozen best): one block per row (grid=6144, TPB=384, 4 float4/thread).
// Spans outside the row's conservative non-zero band (>99.9% of the canvas)
// are pure coalesced STG.128 zero stores; spans inside evaluate the exact
// reference formula. Empty band is encoded as the sentinel interval [0,-1].
//
// Convergence evidence: each replay dirties the full 151 MB canvas, which
// must drain to DRAM once per replay period -> ~5.9-6.0 TB/s sustained DRAM
// write. Eight kernel variants (TPB 256/384/512, persistent grid, int-span
// test, .cs stores, uniform fast-path, two-kernel split, sentinel encoding)
// all measured within the 25.06-26.30us run-noise band with an invariant ncu
// signature (DRAM ~51%, L2 ~56%, issue ~40%, no pipe saturated). Identical
// binaries sampled across rounds span the same band, so remaining variation
// is noise. The output byte count is fixed by the problem, the replay period
// is pinned by write-drain bandwidth, and this kernel is final.

#define H 6144
#define W 6144
#define ROW_F4 (W / 4)          // 1536 float4 per row
#define TPB    384              // 4 float4 per thread

__global__ void __launch_bounds__(TPB) raster_fused_kernel(
    const float* __restrict__ p0_in,
    const float* __restrict__ p1_in,
    float4* __restrict__ out)
{
    const int x = blockIdx.x;           // row
    const int t = threadIdx.x;

    // Segment constants (broadcast loads)
    float p0x = p0_in[0] * (float)H;
    float p0y = p0_in[1] * (float)W;
    float p1x = p1_in[0] * (float)H;
    float p1y = p1_in[1] * (float)W;

    float dx = p1x - p0x;
    float dy = p1y - p0y;
    float len_sq  = dx * dx + dy * dy;
    float inv_len = 1.0f / len_sq;

    float X = (float)x;

    // Conservative band for this row: any pixel (X,y) with dist<1 has its
    // nearest segment point s with |X-sx|<1 and |y-sy|<1. Restrict the segment
    // to sx in (X-1, X+1) -> t-range [tlo,thi]; nonzero y lies within 1 of
    // that sub-segment's y-extent. Empty band -> sentinel [0, -1].
    float ylo = 0.0f, yhi = -1.0f;
    {
        bool has_band;
        float tlo, thi;
        if (fabsf(dx) > 1e-12f) {
            float ta = (X - 1.0f - p0x) / dx;
            float tb = (X + 1.0f - p0x) / dx;
            tlo = fmaxf(fminf(ta, tb), 0.0f);
            thi = fminf(fmaxf(ta, tb), 1.0f);
            has_band = (tlo <= thi);
        } else {
            has_band = (fabsf(X - p0x) < 1.0f);
            tlo = 0.0f; thi = 1.0f;
        }
        if (has_band) {
            float ya = fmaf(tlo, dy, p0y);
            float yb = fmaf(thi, dy, p0y);
            ylo = fminf(ya, yb) - 1.0f;
            yhi = fmaxf(ya, yb) + 1.0f;
        }
    }

    float px  = X - p0x;
    float pxd = px * dx;                      // constant part of dot product

    float4* __restrict__ row = out + (size_t)x * ROW_F4;

    #pragma unroll
    for (int s = 0; s < 4; s++) {             // 4 * 384 = 1536 = ROW_F4
        int   f4 = t + s * TPB;               // float4 index within row
        float a  = (float)(f4 << 2);          // first y of this 4-pixel span

        float4 v = make_float4(0.f, 0.f, 0.f, 0.f);

        // Span [a, a+3] can only hold non-zeros if it meets [ylo, yhi]
        // (unsatisfiable for the sentinel interval).
        if ((yhi >= a) && (ylo <= a + 3.0f)) {
            float* vp = &v.x;
            #pragma unroll
            for (int j = 0; j < 4; j++) {
                float Y  = a + (float)j;
                float py = Y - p0y;
                float tt = (pxd + py * dy) * inv_len;
                tt = fminf(fmaxf(tt, 0.0f), 1.0f);
                float projx = fmaf(tt, dx, p0x);
                float projy = fmaf(tt, dy, p0y);
                float ex = X - projx;
                float ey = Y - projy;
                float dist_sq = ex * ex + ey * ey;
                if (dist_sq < 1.0f) {
                    vp[j] = 1.0f - sqrtf(dist_sq);
                }
            }
        }

        row[f4] = v;                          // coalesced STG.128
    }
}

extern "C" void kernel_launch(void* const* d_in, const int* in_sizes, int n_in,
                              void* d_out, int out_size) {
    (void)in_sizes; (void)n_in; (void)out_size;
    const float* p0 = (const float*)d_in[0];
    const float* p1 = (const float*)d_in[1];
    float4* out = (float4*)d_out;

    raster_fused_kernel<<<H, TPB>>>(p0, p1, out);
}